// round 13
// baseline (speedup 1.0000x reference)
#include <cuda_runtime.h>
#include <math.h>

#define NB   64
#define NN   512
#define NC   128
#define NFS  16
#define NRES 511
#define NBN  (NB*NN)
#define TR   32
#define TROWS (TR + NFS - 1)   // 47 tile rows

// Scratch (no allocations allowed)
__device__ int   g_order[NBN];
__device__ float g_sr[NBN];
__device__ float g_dsrc[NBN];
__device__ float g_ddst[NBN];
__device__ float g_nxp[NBN];         // |x|^2, permuted by sort rank
__device__ float g_wv[NB*NRES];
__device__ int   g_exit[NBN];        // exit position from every start p
__device__ unsigned g_maskf[NBN];    // visited-bits within segment from p

// ===== K1: fused per-node scores + per-batch sort (grid=NB, 512 threads) ====
__global__ void k_scores_sort(const float* __restrict__ x,
                              const float* __restrict__ sw,
                              const float* __restrict__ ap) {
    __shared__ __align__(16) float sp[128][4][4];   // 8 KB partials
    __shared__ float s_sc[NN], s_ps[NN], s_pd[NN], s_nx[NN];
    __shared__ unsigned long long sk[NN];
    __shared__ float s_wn;
    int b = blockIdx.x, t = threadIdx.x, w = t >> 5, lane = t & 31;

    float4 wv4 = *(const float4*)(sw + lane * 4);
    float4 as4 = *(const float4*)(ap + lane * 4);
    float4 ad4 = *(const float4*)(ap + NC + lane * 4);

    if (w == 0) {   // ||w||^2 once
        float wn = wv4.x*wv4.x + wv4.y*wv4.y + wv4.z*wv4.z + wv4.w*wv4.w;
        #pragma unroll
        for (int o = 16; o; o >>= 1) wn += __shfl_xor_sync(0xffffffffu, wn, o);
        if (lane == 0) s_wn = wn;
    }
    __syncthreads();
    float inv_nw = rsqrtf(s_wn);

    // scores: 4 rounds x (16 warps x 8 nodes)
    for (int rd = 0; rd < 4; rd++) {
        #pragma unroll
        for (int it = 0; it < 8; it++) {
            int nl = rd * 128 + w * 8 + it;       // local node 0..511
            float4 xv = *(const float4*)(x + (size_t)(b * NN + nl) * NC + lane * 4);
            float s  = xv.x*wv4.x + xv.y*wv4.y + xv.z*wv4.z + xv.w*wv4.w;
            float ps = xv.x*as4.x + xv.y*as4.y + xv.z*as4.z + xv.w*as4.w;
            float pd = xv.x*ad4.x + xv.y*ad4.y + xv.z*ad4.z + xv.w*ad4.w;
            float nx = xv.x*xv.x + xv.y*xv.y + xv.z*xv.z + xv.w*xv.w;
            #pragma unroll
            for (int o = 16; o >= 4; o >>= 1) {
                s  += __shfl_xor_sync(0xffffffffu, s,  o);
                ps += __shfl_xor_sync(0xffffffffu, ps, o);
                pd += __shfl_xor_sync(0xffffffffu, pd, o);
                nx += __shfl_xor_sync(0xffffffffu, nx, o);
            }
            if (lane < 4) {
                int pn = w * 8 + it;
                sp[pn][0][lane] = s;  sp[pn][1][lane] = ps;
                sp[pn][2][lane] = pd; sp[pn][3][lane] = nx;
            }
        }
        __syncthreads();
        {
            int pn = t >> 2, v = t & 3;
            float4 q = *(const float4*)sp[pn][v];
            float r = (q.x + q.y) + (q.z + q.w);
            int nl = rd * 128 + pn;
            if      (v == 0) s_sc[nl] = r * inv_nw;   // normalized score
            else if (v == 1) s_ps[nl] = r;
            else if (v == 2) s_pd[nl] = r;
            else             s_nx[nl] = r;
        }
        __syncthreads();
    }

    // register-resident bitonic sort (desc score, asc index)
    float sval = s_sc[t];
    unsigned u = __float_as_uint(sval);
    u = (u & 0x80000000u) ? ~u : (u | 0x80000000u);
    u = ~u;
    unsigned long long key = ((unsigned long long)u << 32) | (unsigned)t;

    #pragma unroll
    for (int k = 2; k <= NN; k <<= 1) {
        #pragma unroll
        for (int j = k >> 1; j > 0; j >>= 1) {
            unsigned long long other;
            if (j >= 32) {
                __syncthreads();
                sk[t] = key;
                __syncthreads();
                other = sk[t ^ j];
            } else {
                other = __shfl_xor_sync(0xffffffffu, key, j);
            }
            bool takeMin = (((t & j) == 0) == ((t & k) == 0));
            bool less = key < other;
            key = (takeMin == less) ? key : other;
        }
    }

    int idx = (int)(key & 0xffffffffu);
    g_order[b * NN + t] = idx;
    g_sr[b * NN + t]    = tanhf(s_sc[idx]);
    g_dsrc[b * NN + t]  = s_ps[idx];
    g_ddst[b * NN + t]  = s_pd[idx];
    g_nxp[b * NN + t]   = s_nx[idx];
}

// -------- K2: banded window via dot identity + exit/mask tail --------
__global__ void k_windows(const float* __restrict__ x,
                          const int*   __restrict__ ep) {
    __shared__ __align__(16) float tile[TROWS * NC];    // 24064 B
    __shared__ __align__(16) float sp8[TR * 15 * 8];    // 15360 B
    __shared__ __align__(16) float skk[TR * 15];        // 1920 B
    __shared__ __align__(16) float sddst[48];
    __shared__ __align__(16) float snx[48];
    __shared__ int sjmp[TR];
    int b  = blockIdx.y;
    int r0 = blockIdx.x * TR;
    int t = threadIdx.x, w = t >> 5, lane = t & 31;
    const int* ord = g_order + b * NN;

    for (int rr = w; rr < TROWS; rr += 8) {
        int gr  = r0 + rr;
        int grc = gr < NN ? gr : (NN - 1);
        int id  = ord[grc];
        float4 v = *(const float4*)(x + ((size_t)(b * NN + id)) * NC + lane * 4);
        *(float4*)(tile + rr * NC + lane * 4) = v;
    }
    if (t < TROWS) {
        int gr  = r0 + t;
        int grc = gr < NN ? gr : (NN - 1);
        sddst[t] = g_ddst[b * NN + grc];
        snx[t]   = g_nxp[b * NN + grc];   // permuted: linear load
    }
    __syncthreads();

    // Phase A: dot products only (identity form), warp w owns 4 source rows
    int rbase = w * 4;
    float4 xs0 = *(const float4*)(tile + (rbase + 0) * NC + lane * 4);
    float4 xs1 = *(const float4*)(tile + (rbase + 1) * NC + lane * 4);
    float4 xs2 = *(const float4*)(tile + (rbase + 2) * NC + lane * 4);
    float4 xs3 = *(const float4*)(tile + (rbase + 3) * NC + lane * 4);

    #pragma unroll
    for (int dd = 1; dd <= 18; dd++) {
        float4 xd = *(const float4*)(tile + (rbase + dd) * NC + lane * 4);
        #pragma unroll
        for (int i = 0; i < 4; i++) {
            int j = dd - i;
            if (j >= 1 && j <= 15) {
                float4 xs = (i == 0) ? xs0 : (i == 1) ? xs1 : (i == 2) ? xs2 : xs3;
                float p = xs.x*xd.x + xs.y*xd.y + xs.z*xd.z + xs.w*xd.w;
                p += __shfl_xor_sync(0xffffffffu, p, 16);
                p += __shfl_xor_sync(0xffffffffu, p, 8);
                if (lane < 8)
                    sp8[((rbase + i) * 15 + (j - 1)) * 8 + lane] = p;
            }
        }
    }
    __syncthreads();

    // Phase B1: d2 = nx_s + nx_d - 2*dot ; kk = exp(-sqrt(d2)/2) - EPS
    for (int i = t; i < TR * 15; i += 256) {
        int rl = i / 15, jm1 = i - rl * 15;
        bool valid = (r0 + rl + jm1 + 1) < NN;
        float4 a  = *(const float4*)(sp8 + i * 8);
        float4 b4 = *(const float4*)(sp8 + i * 8 + 4);
        float dot = ((a.x + a.y) + (a.z + a.w)) + ((b4.x + b4.y) + (b4.z + b4.w));
        float d2 = fmaxf(snx[rl] + snx[rl + jm1 + 1] - 2.0f * dot, 0.0f);
        skk[i] = valid ? (expf(-0.5f * sqrtf(d2)) - 1e-20f) : -1e-20f;
    }
    __syncthreads();

    // Phase B2: thread-per-r softmax / max / argmax
    if (t < TR) {
        int r = r0 + t;
        if (r < NRES) {
            int epoch = *ep;
            float tau = (float)(10.0 * exp((double)epoch * -0.046051701859880914));
            float dsr = g_dsrc[b * NN + r];

            float att[16], kk[16];
            kk[0]  = 1.0f;
            att[0] = dsr + sddst[t];
            #pragma unroll
            for (int j = 1; j < NFS; j++) {
                bool valid = (r + j) < NN;
                kk[j]  = skk[t * 15 + (j - 1)];
                att[j] = valid ? (dsr + sddst[t + j]) : -1e9f;
            }
            float m = att[0];
            #pragma unroll
            for (int j = 1; j < NFS; j++) m = fmaxf(m, att[j]);
            float e[16], ssum = 0.0f;
            #pragma unroll
            for (int j = 0; j < NFS; j++) { e[j] = expf((att[j] - m) / tau); ssum += e[j]; }
            float inv = 1.0f / ssum;

            float wrow = -1e9f, best = -3e9f;
            int bj = 1;
            #pragma unroll
            for (int j = 0; j < NFS; j++) {
                bool valid = (r + j) < NN;
                float q  = kk[j] * (e[j] * inv);
                float qm = valid ? q : -1e9f;
                wrow = fmaxf(wrow, qm);
                if (j >= 1 && qm > best) { best = qm; bj = j; }
            }
            g_wv[b * NRES + r] = wrow * g_sr[b * NN + r];
            sjmp[t] = bj;
        }
    }
    __syncthreads();

    // Tail: per-position within-segment exit + visited mask
    if (t < TR) {
        int r = r0 + t;
        if (r < NRES) {
            int e = r0 + TR; if (e > NRES) e = NRES;
            unsigned m = 0u;
            int p = r;
            while (p < e) { m |= 1u << (p - r0); p += sjmp[p - r0]; }
            g_exit[b * NN + r]  = p;
            g_maskf[b * NN + r] = m;
        }
    }
}

// -------- K3: staged chain + parallel compaction + pipelined gather ----
__global__ void k_chain(const float* __restrict__ x, float* __restrict__ out) {
    __shared__ float swv[NRES];
    __shared__ int   sord[NRES];
    __shared__ int   sexit[NRES];
    __shared__ int   sentry[16];
    __shared__ unsigned smask[16];
    __shared__ int   scnt[17];
    __shared__ int   sidx[NRES + 64];
    __shared__ float swt2[NRES + 64];
    __shared__ __align__(16) float part[16][NC];
    int b = blockIdx.x, t = threadIdx.x, w = t >> 5, lane = t & 31;  // 512 thr

    if (t < NRES) {
        swv[t]   = g_wv[b * NRES + t];
        sord[t]  = g_order[b * NN + t];
        sexit[t] = g_exit[b * NN + t];
    }
    if (t < 16) sentry[t] = -1;
    __syncthreads();

    // segment-to-segment hop: <=16 dependent LDS
    if (t == 0) {
        int p = 0;
        while (p < NRES) { sentry[p >> 5] = p; p = sexit[p]; }
    }
    __syncthreads();

    // entry masks straight from L2 (16 parallel LDG)
    if (t < 16) {
        int e = sentry[t];
        unsigned m = (e >= 0) ? g_maskf[b * NN + e] : 0u;
        smask[t] = m;
        scnt[t]  = __popc(m);
    }
    __syncthreads();
    if (t == 0) {
        int a = 0;
        #pragma unroll
        for (int i = 0; i < 16; i++) { int c = scnt[i]; scnt[i] = a; a += c; }
        scnt[16] = a;
    }
    __syncthreads();

    // fully parallel compaction from staged SMEM arrays
    if (t < NRES) {
        unsigned m = smask[t >> 5];
        if ((m >> (t & 31)) & 1u) {
            int slot = scnt[t >> 5] + __popc(m & ((1u << (t & 31)) - 1u));
            sidx[slot] = sord[t];
            swt2[slot] = swv[t];
        }
    }
    if (t >= 64 && t < 128) {   // zero-pad tail for over-read
        int n0 = scnt[16], k = t - 64;
        sidx[n0 + k] = 0;
        swt2[n0 + k] = 0.0f;
    }
    __syncthreads();

    // pipelined gather: each warp takes chunks of 4 independent rows
    int n = scnt[16];
    const float* xb = x + (size_t)b * NN * NC;
    float ax = 0.f, ay = 0.f, az = 0.f, a4 = 0.f;
    for (int base = w * 4; base < n; base += 64) {
        float u0 = swt2[base + 0], u1 = swt2[base + 1];
        float u2 = swt2[base + 2], u3 = swt2[base + 3];
        float4 v0 = *(const float4*)(xb + (size_t)sidx[base + 0] * NC + lane * 4);
        float4 v1 = *(const float4*)(xb + (size_t)sidx[base + 1] * NC + lane * 4);
        float4 v2 = *(const float4*)(xb + (size_t)sidx[base + 2] * NC + lane * 4);
        float4 v3 = *(const float4*)(xb + (size_t)sidx[base + 3] * NC + lane * 4);
        ax += u0*v0.x + u1*v1.x + u2*v2.x + u3*v3.x;
        ay += u0*v0.y + u1*v1.y + u2*v2.y + u3*v3.y;
        az += u0*v0.z + u1*v1.z + u2*v2.z + u3*v3.z;
        a4 += u0*v0.w + u1*v1.w + u2*v2.w + u3*v3.w;
    }
    part[w][lane * 4 + 0] = ax;
    part[w][lane * 4 + 1] = ay;
    part[w][lane * 4 + 2] = az;
    part[w][lane * 4 + 3] = a4;
    __syncthreads();

    if (t < NC) {
        float s = 0.0f;
        #pragma unroll
        for (int w2 = 0; w2 < 16; w2++) s += part[w2][t];
        out[b * NC + t] = s;
    }
}

extern "C" void kernel_launch(void* const* d_in, const int* in_sizes, int n_in,
                              void* d_out, int out_size) {
    const float* x   = (const float*)d_in[0];
    // d_in[1] = edge_index (unused by the reference forward pass)
    const float* sw  = (const float*)d_in[2];
    const float* ap  = (const float*)d_in[3];
    const int*   ep  = (const int*)d_in[4];
    float* out = (float*)d_out;

    k_scores_sort<<<NB, 512>>>(x, sw, ap);
    dim3 gw((NRES + TR - 1) / TR, NB);
    k_windows<<<gw, 256>>>(x, ep);
    k_chain<<<NB, 512>>>(x, out);
}

// round 14
// speedup vs baseline: 1.3816x; 1.3816x over previous
#include <cuda_runtime.h>
#include <math.h>

#define NB   64
#define NN   512
#define NC   128
#define NFS  16
#define NRES 511
#define NBN  (NB*NN)
#define TR   32
#define TROWS (TR + NFS - 1)   // 47 tile rows

// Scratch (no allocations allowed)
__device__ float g_score[NBN];
__device__ float g_ssrc[NBN];
__device__ float g_sdst[NBN];
__device__ float g_nx[NBN];          // |x|^2 per node
__device__ int   g_order[NBN];
__device__ float g_sr[NBN];
__device__ float g_dsrc[NBN];
__device__ float g_ddst[NBN];
__device__ float g_wv[NB*NRES];
__device__ int   g_exit[NBN];        // exit position from every start p
__device__ unsigned g_maskf[NBN];    // visited-bits within segment from p

// -------- Kernel 1: per-node score + attention dots + |x|^2 --------
__global__ void k_scores(const float* __restrict__ x,
                         const float* __restrict__ sw,
                         const float* __restrict__ ap) {
    __shared__ float sp[8][5][8];
    __shared__ float sfin[8][5];
    int t = threadIdx.x, w = t >> 5, lane = t & 31;
    int node = blockIdx.x * 8 + w;

    float4 xv = *(const float4*)(x  + (size_t)node * NC + lane * 4);
    float4 wv = *(const float4*)(sw + lane * 4);
    float4 as = *(const float4*)(ap + lane * 4);
    float4 ad = *(const float4*)(ap + NC + lane * 4);
    float s  = xv.x*wv.x + xv.y*wv.y + xv.z*wv.z + xv.w*wv.w;
    float ps = xv.x*as.x + xv.y*as.y + xv.z*as.z + xv.w*as.w;
    float pd = xv.x*ad.x + xv.y*ad.y + xv.z*ad.z + xv.w*ad.w;
    float wn = wv.x*wv.x + wv.y*wv.y + wv.z*wv.z + wv.w*wv.w;
    float nx = xv.x*xv.x + xv.y*xv.y + xv.z*xv.z + xv.w*xv.w;
    #pragma unroll
    for (int o = 16; o >= 8; o >>= 1) {
        s  += __shfl_xor_sync(0xffffffffu, s,  o);
        ps += __shfl_xor_sync(0xffffffffu, ps, o);
        pd += __shfl_xor_sync(0xffffffffu, pd, o);
        wn += __shfl_xor_sync(0xffffffffu, wn, o);
        nx += __shfl_xor_sync(0xffffffffu, nx, o);
    }
    if (lane < 8) {
        sp[w][0][lane] = s;  sp[w][1][lane] = ps;
        sp[w][2][lane] = pd; sp[w][3][lane] = wn;
        sp[w][4][lane] = nx;
    }
    __syncthreads();
    if (t < 40) {
        int nd = t / 5, v = t - nd * 5;
        const float* q = sp[nd][v];
        sfin[nd][v] = ((q[0]+q[1])+(q[2]+q[3])) + ((q[4]+q[5])+(q[6]+q[7]));
    }
    __syncthreads();
    if (t < 8) {
        int gn = blockIdx.x * 8 + t;
        g_score[gn] = sfin[t][0] / sqrtf(sfin[t][3]);
        g_ssrc[gn]  = sfin[t][1];
        g_sdst[gn]  = sfin[t][2];
        g_nx[gn]    = sfin[t][4];
    }
}

// -------- Kernel 2: register-resident bitonic sort with u64 keys --------
__global__ void k_sort() {
    __shared__ unsigned long long sk[NN];
    int b = blockIdx.x, t = threadIdx.x;

#if __CUDA_ARCH__ >= 900
    cudaGridDependencySynchronize();    // PDL: wait for k_scores results
#endif

    float sval = g_score[b * NN + t];
    unsigned u = __float_as_uint(sval);
    u = (u & 0x80000000u) ? ~u : (u | 0x80000000u);
    u = ~u;
    unsigned long long key = ((unsigned long long)u << 32) | (unsigned)t;

    #pragma unroll
    for (int k = 2; k <= NN; k <<= 1) {
        #pragma unroll
        for (int j = k >> 1; j > 0; j >>= 1) {
            unsigned long long other;
            if (j >= 32) {
                __syncthreads();
                sk[t] = key;
                __syncthreads();
                other = sk[t ^ j];
            } else {
                other = __shfl_xor_sync(0xffffffffu, key, j);
            }
            bool takeMin = (((t & j) == 0) == ((t & k) == 0));
            bool less = key < other;
            key = (takeMin == less) ? key : other;
        }
    }

    int idx = (int)(key & 0xffffffffu);
    int gi  = b * NN + idx;
    g_order[b * NN + t] = idx;
    g_sr[b * NN + t]    = tanhf(g_score[gi]);
    g_dsrc[b * NN + t]  = g_ssrc[gi];
    g_ddst[b * NN + t]  = g_sdst[gi];
}

// -------- Kernel 3: banded window via dot identity + exit/mask tail --------
__global__ void k_windows(const float* __restrict__ x,
                          const int*   __restrict__ ep) {
    __shared__ __align__(16) float tile[TROWS * NC];    // 24064 B
    __shared__ __align__(16) float sp8[TR * 15 * 8];    // 15360 B
    __shared__ __align__(16) float skk[TR * 15];        // 1920 B
    __shared__ __align__(16) float sddst[48];
    __shared__ __align__(16) float snx[48];
    __shared__ int sjmp[TR];
    int b  = blockIdx.y;
    int r0 = blockIdx.x * TR;
    int t = threadIdx.x, w = t >> 5, lane = t & 31;

    // pre-sync prologue: epoch-independent setup
    int epoch = *ep;   // input buffer, not written by predecessors
    float tau = (float)(10.0 * exp((double)epoch * -0.046051701859880914));

#if __CUDA_ARCH__ >= 900
    cudaGridDependencySynchronize();    // PDL: wait for k_sort results
#endif

    const int* ord = g_order + b * NN;

    for (int rr = w; rr < TROWS; rr += 8) {
        int gr  = r0 + rr;
        int grc = gr < NN ? gr : (NN - 1);
        int id  = ord[grc];
        float4 v = *(const float4*)(x + ((size_t)(b * NN + id)) * NC + lane * 4);
        *(float4*)(tile + rr * NC + lane * 4) = v;
    }
    if (t < TROWS) {
        int gr  = r0 + t;
        int grc = gr < NN ? gr : (NN - 1);
        sddst[t] = g_ddst[b * NN + grc];
        snx[t]   = g_nx[b * NN + ord[grc]];
    }
    __syncthreads();

    // Phase A: dot products only (identity form), warp w owns 4 source rows
    int rbase = w * 4;
    float4 xs0 = *(const float4*)(tile + (rbase + 0) * NC + lane * 4);
    float4 xs1 = *(const float4*)(tile + (rbase + 1) * NC + lane * 4);
    float4 xs2 = *(const float4*)(tile + (rbase + 2) * NC + lane * 4);
    float4 xs3 = *(const float4*)(tile + (rbase + 3) * NC + lane * 4);

    #pragma unroll
    for (int dd = 1; dd <= 18; dd++) {
        float4 xd = *(const float4*)(tile + (rbase + dd) * NC + lane * 4);
        #pragma unroll
        for (int i = 0; i < 4; i++) {
            int j = dd - i;
            if (j >= 1 && j <= 15) {
                float4 xs = (i == 0) ? xs0 : (i == 1) ? xs1 : (i == 2) ? xs2 : xs3;
                float p = xs.x*xd.x + xs.y*xd.y + xs.z*xd.z + xs.w*xd.w;
                p += __shfl_xor_sync(0xffffffffu, p, 16);
                p += __shfl_xor_sync(0xffffffffu, p, 8);
                if (lane < 8)
                    sp8[((rbase + i) * 15 + (j - 1)) * 8 + lane] = p;
            }
        }
    }
    __syncthreads();

    // Phase B1: d2 = nx_s + nx_d - 2*dot ; kk = exp(-sqrt(d2)/2) - EPS
    for (int i = t; i < TR * 15; i += 256) {
        int rl = i / 15, jm1 = i - rl * 15;
        bool valid = (r0 + rl + jm1 + 1) < NN;
        float4 a  = *(const float4*)(sp8 + i * 8);
        float4 b4 = *(const float4*)(sp8 + i * 8 + 4);
        float dot = ((a.x + a.y) + (a.z + a.w)) + ((b4.x + b4.y) + (b4.z + b4.w));
        float d2 = fmaxf(snx[rl] + snx[rl + jm1 + 1] - 2.0f * dot, 0.0f);
        skk[i] = valid ? (expf(-0.5f * sqrtf(d2)) - 1e-20f) : -1e-20f;
    }
    __syncthreads();

    // Phase B2: thread-per-r softmax / max / argmax
    if (t < TR) {
        int r = r0 + t;
        if (r < NRES) {
            float dsr = g_dsrc[b * NN + r];

            float att[16], kk[16];
            kk[0]  = 1.0f;
            att[0] = dsr + sddst[t];
            #pragma unroll
            for (int j = 1; j < NFS; j++) {
                bool valid = (r + j) < NN;
                kk[j]  = skk[t * 15 + (j - 1)];
                att[j] = valid ? (dsr + sddst[t + j]) : -1e9f;
            }
            float m = att[0];
            #pragma unroll
            for (int j = 1; j < NFS; j++) m = fmaxf(m, att[j]);
            float e[16], ssum = 0.0f;
            #pragma unroll
            for (int j = 0; j < NFS; j++) { e[j] = expf((att[j] - m) / tau); ssum += e[j]; }
            float inv = 1.0f / ssum;

            float wrow = -1e9f, best = -3e9f;
            int bj = 1;
            #pragma unroll
            for (int j = 0; j < NFS; j++) {
                bool valid = (r + j) < NN;
                float q  = kk[j] * (e[j] * inv);
                float qm = valid ? q : -1e9f;
                wrow = fmaxf(wrow, qm);
                if (j >= 1 && qm > best) { best = qm; bj = j; }
            }
            g_wv[b * NRES + r] = wrow * g_sr[b * NN + r];
            sjmp[t] = bj;
        }
    }
    __syncthreads();

    // Tail: per-position within-segment exit + visited mask
    if (t < TR) {
        int r = r0 + t;
        if (r < NRES) {
            int e = r0 + TR; if (e > NRES) e = NRES;
            unsigned m = 0u;
            int p = r;
            while (p < e) { m |= 1u << (p - r0); p += sjmp[p - r0]; }
            g_exit[b * NN + r]  = p;
            g_maskf[b * NN + r] = m;
        }
    }
}

// -------- Kernel 4: staged chain + parallel compaction + pipelined gather ----
__global__ void k_chain(const float* __restrict__ x, float* __restrict__ out) {
    __shared__ float swv[NRES];
    __shared__ int   sord[NRES];
    __shared__ int   sexit[NRES];
    __shared__ int   sentry[16];
    __shared__ unsigned smask[16];
    __shared__ int   scnt[17];
    __shared__ int   sidx[NRES + 64];
    __shared__ float swt2[NRES + 64];
    __shared__ __align__(16) float part[16][NC];
    int b = blockIdx.x, t = threadIdx.x, w = t >> 5, lane = t & 31;  // 512 thr

    if (t < 16) sentry[t] = -1;

#if __CUDA_ARCH__ >= 900
    cudaGridDependencySynchronize();    // PDL: wait for k_windows results
#endif

    if (t < NRES) {
        swv[t]   = g_wv[b * NRES + t];
        sord[t]  = g_order[b * NN + t];
        sexit[t] = g_exit[b * NN + t];
    }
    __syncthreads();

    // segment-to-segment hop: <=16 dependent LDS
    if (t == 0) {
        int p = 0;
        while (p < NRES) { sentry[p >> 5] = p; p = sexit[p]; }
    }
    __syncthreads();

    // entry masks straight from L2 (16 parallel LDG)
    if (t < 16) {
        int e = sentry[t];
        unsigned m = (e >= 0) ? g_maskf[b * NN + e] : 0u;
        smask[t] = m;
        scnt[t]  = __popc(m);
    }
    __syncthreads();
    if (t == 0) {
        int a = 0;
        #pragma unroll
        for (int i = 0; i < 16; i++) { int c = scnt[i]; scnt[i] = a; a += c; }
        scnt[16] = a;
    }
    __syncthreads();

    // fully parallel compaction from staged SMEM arrays
    if (t < NRES) {
        unsigned m = smask[t >> 5];
        if ((m >> (t & 31)) & 1u) {
            int slot = scnt[t >> 5] + __popc(m & ((1u << (t & 31)) - 1u));
            sidx[slot] = sord[t];
            swt2[slot] = swv[t];
        }
    }
    if (t >= 64 && t < 128) {   // zero-pad tail for over-read
        int n0 = scnt[16], k = t - 64;
        sidx[n0 + k] = 0;
        swt2[n0 + k] = 0.0f;
    }
    __syncthreads();

    // pipelined gather: each warp takes chunks of 4 independent rows
    int n = scnt[16];
    const float* xb = x + (size_t)b * NN * NC;
    float ax = 0.f, ay = 0.f, az = 0.f, a4 = 0.f;
    for (int base = w * 4; base < n; base += 64) {
        float u0 = swt2[base + 0], u1 = swt2[base + 1];
        float u2 = swt2[base + 2], u3 = swt2[base + 3];
        float4 v0 = *(const float4*)(xb + (size_t)sidx[base + 0] * NC + lane * 4);
        float4 v1 = *(const float4*)(xb + (size_t)sidx[base + 1] * NC + lane * 4);
        float4 v2 = *(const float4*)(xb + (size_t)sidx[base + 2] * NC + lane * 4);
        float4 v3 = *(const float4*)(xb + (size_t)sidx[base + 3] * NC + lane * 4);
        ax += u0*v0.x + u1*v1.x + u2*v2.x + u3*v3.x;
        ay += u0*v0.y + u1*v1.y + u2*v2.y + u3*v3.y;
        az += u0*v0.z + u1*v1.z + u2*v2.z + u3*v3.z;
        a4 += u0*v0.w + u1*v1.w + u2*v2.w + u3*v3.w;
    }
    part[w][lane * 4 + 0] = ax;
    part[w][lane * 4 + 1] = ay;
    part[w][lane * 4 + 2] = az;
    part[w][lane * 4 + 3] = a4;
    __syncthreads();

    if (t < NC) {
        float s = 0.0f;
        #pragma unroll
        for (int w2 = 0; w2 < 16; w2++) s += part[w2][t];
        out[b * NC + t] = s;
    }
}

// ---- PDL launch helper: consumer may start while producer drains ----
static void launch_pdl(const void* func, dim3 grid, dim3 block, void** args) {
    cudaLaunchConfig_t cfg = {};
    cfg.gridDim  = grid;
    cfg.blockDim = block;
    cfg.stream   = 0;
    cudaLaunchAttribute attr[1];
    attr[0].id = cudaLaunchAttributeProgrammaticStreamSerialization;
    attr[0].val.programmaticStreamSerializationAllowed = 1;
    cfg.attrs    = attr;
    cfg.numAttrs = 1;
    cudaLaunchKernelExC(&cfg, func, args);
}

extern "C" void kernel_launch(void* const* d_in, const int* in_sizes, int n_in,
                              void* d_out, int out_size) {
    const float* x   = (const float*)d_in[0];
    // d_in[1] = edge_index (unused by the reference forward pass)
    const float* sw  = (const float*)d_in[2];
    const float* ap  = (const float*)d_in[3];
    const int*   ep  = (const int*)d_in[4];
    float* out = (float*)d_out;

    k_scores<<<NBN / 8, 256>>>(x, sw, ap);

    {   // k_sort with PDL
        void* args[] = {};
        launch_pdl((const void*)k_sort, dim3(NB), dim3(NN), args);
    }
    {   // k_windows with PDL
        void* a0 = (void*)x; void* a1 = (void*)ep;
        void* args[] = { &a0, &a1 };
        dim3 gw((NRES + TR - 1) / TR, NB);
        launch_pdl((const void*)k_windows, gw, dim3(256), args);
    }
    {   // k_chain with PDL
        void* a0 = (void*)x; void* a1 = (void*)out;
        void* args[] = { &a0, &a1 };
        launch_pdl((const void*)k_chain, dim3(NB), dim3(512), args);
    }
}

// round 15
// speedup vs baseline: 1.6074x; 1.1634x over previous
#include <cuda_runtime.h>
#include <math.h>

#define NB   64
#define NN   512
#define NC   128
#define NFS  16
#define NRES 511
#define NBN  (NB*NN)
#define TR   32
#define TROWS (TR + NFS - 1)   // 47 tile rows

// Scratch (no allocations allowed)
__device__ float g_score[NBN];
__device__ float g_ssrc[NBN];
__device__ float g_sdst[NBN];
__device__ float g_nx[NBN];          // |x|^2 per node
__device__ int   g_order[NBN];
__device__ float g_sr[NBN];
__device__ float g_dsrc[NBN];
__device__ float g_ddst[NBN];
__device__ float g_wv[NB*NRES];
__device__ int   g_exit[NBN];        // exit position from every start p
__device__ unsigned g_maskf[NBN];    // visited-bits within segment from p

// -------- Kernel 1: per-node score + attention dots + |x|^2 --------
__global__ void k_scores(const float* __restrict__ x,
                         const float* __restrict__ sw,
                         const float* __restrict__ ap) {
    __shared__ float sp[8][5][8];
    __shared__ float sfin[8][5];
    int t = threadIdx.x, w = t >> 5, lane = t & 31;
    int node = blockIdx.x * 8 + w;

    float4 xv = *(const float4*)(x  + (size_t)node * NC + lane * 4);
    float4 wv = *(const float4*)(sw + lane * 4);
    float4 as = *(const float4*)(ap + lane * 4);
    float4 ad = *(const float4*)(ap + NC + lane * 4);
    float s  = xv.x*wv.x + xv.y*wv.y + xv.z*wv.z + xv.w*wv.w;
    float ps = xv.x*as.x + xv.y*as.y + xv.z*as.z + xv.w*as.w;
    float pd = xv.x*ad.x + xv.y*ad.y + xv.z*ad.z + xv.w*ad.w;
    float wn = wv.x*wv.x + wv.y*wv.y + wv.z*wv.z + wv.w*wv.w;
    float nx = xv.x*xv.x + xv.y*xv.y + xv.z*xv.z + xv.w*xv.w;
    #pragma unroll
    for (int o = 16; o >= 8; o >>= 1) {
        s  += __shfl_xor_sync(0xffffffffu, s,  o);
        ps += __shfl_xor_sync(0xffffffffu, ps, o);
        pd += __shfl_xor_sync(0xffffffffu, pd, o);
        wn += __shfl_xor_sync(0xffffffffu, wn, o);
        nx += __shfl_xor_sync(0xffffffffu, nx, o);
    }
    if (lane < 8) {
        sp[w][0][lane] = s;  sp[w][1][lane] = ps;
        sp[w][2][lane] = pd; sp[w][3][lane] = wn;
        sp[w][4][lane] = nx;
    }
    __syncthreads();
    if (t < 40) {
        int nd = t / 5, v = t - nd * 5;
        const float* q = sp[nd][v];
        sfin[nd][v] = ((q[0]+q[1])+(q[2]+q[3])) + ((q[4]+q[5])+(q[6]+q[7]));
    }
    __syncthreads();
    if (t < 8) {
        int gn = blockIdx.x * 8 + t;
        g_score[gn] = sfin[t][0] / sqrtf(sfin[t][3]);
        g_ssrc[gn]  = sfin[t][1];
        g_sdst[gn]  = sfin[t][2];
        g_nx[gn]    = sfin[t][4];
    }
}

// -------- Kernel 2: register-resident bitonic sort with u64 keys --------
__global__ void k_sort() {
    __shared__ unsigned long long sk[NN];
    int b = blockIdx.x, t = threadIdx.x;
    float sval = g_score[b * NN + t];
    unsigned u = __float_as_uint(sval);
    u = (u & 0x80000000u) ? ~u : (u | 0x80000000u);
    u = ~u;
    unsigned long long key = ((unsigned long long)u << 32) | (unsigned)t;

    #pragma unroll
    for (int k = 2; k <= NN; k <<= 1) {
        #pragma unroll
        for (int j = k >> 1; j > 0; j >>= 1) {
            unsigned long long other;
            if (j >= 32) {
                __syncthreads();
                sk[t] = key;
                __syncthreads();
                other = sk[t ^ j];
            } else {
                other = __shfl_xor_sync(0xffffffffu, key, j);
            }
            bool takeMin = (((t & j) == 0) == ((t & k) == 0));
            bool less = key < other;
            key = (takeMin == less) ? key : other;
        }
    }

    int idx = (int)(key & 0xffffffffu);
    int gi  = b * NN + idx;
    g_order[b * NN + t] = idx;
    g_sr[b * NN + t]    = tanhf(g_score[gi]);
    g_dsrc[b * NN + t]  = g_ssrc[gi];
    g_ddst[b * NN + t]  = g_sdst[gi];
}

// -------- Kernel 3: banded window, log-space max/argmax --------
__global__ void k_windows(const float* __restrict__ x,
                          const int*   __restrict__ ep) {
    __shared__ __align__(16) float tile[TROWS * NC];    // 24064 B
    __shared__ __align__(16) float sp8[TR * 15 * 8];    // 15360 B (reused B2)
    __shared__ __align__(16) float skk[TR * 15];        // -d/2 per (r,j)
    __shared__ __align__(16) float sddst[48];
    __shared__ __align__(16) float snx[48];
    __shared__ float sdsrc[TR];
    __shared__ float sm[TR];
    __shared__ int sjmp[TR];
    int b  = blockIdx.y;
    int r0 = blockIdx.x * TR;
    int t = threadIdx.x, w = t >> 5, lane = t & 31;

    int epoch = *ep;
    float tau = (float)(10.0 * exp((double)epoch * -0.046051701859880914));
    float invtau = 1.0f / tau;

    const int* ord = g_order + b * NN;

    for (int rr = w; rr < TROWS; rr += 8) {
        int gr  = r0 + rr;
        int grc = gr < NN ? gr : (NN - 1);
        int id  = ord[grc];
        float4 v = *(const float4*)(x + ((size_t)(b * NN + id)) * NC + lane * 4);
        *(float4*)(tile + rr * NC + lane * 4) = v;
    }
    if (t < TROWS) {
        int gr  = r0 + t;
        int grc = gr < NN ? gr : (NN - 1);
        sddst[t] = g_ddst[b * NN + grc];
        snx[t]   = g_nx[b * NN + ord[grc]];
    }
    if (t < TR) sdsrc[t] = g_dsrc[b * NN + ((r0 + t < NN) ? (r0 + t) : (NN - 1))];
    __syncthreads();

    // Phase A: dot products (identity form), warp w owns 4 source rows
    int rbase = w * 4;
    float4 xs0 = *(const float4*)(tile + (rbase + 0) * NC + lane * 4);
    float4 xs1 = *(const float4*)(tile + (rbase + 1) * NC + lane * 4);
    float4 xs2 = *(const float4*)(tile + (rbase + 2) * NC + lane * 4);
    float4 xs3 = *(const float4*)(tile + (rbase + 3) * NC + lane * 4);

    #pragma unroll
    for (int dd = 1; dd <= 18; dd++) {
        float4 xd = *(const float4*)(tile + (rbase + dd) * NC + lane * 4);
        #pragma unroll
        for (int i = 0; i < 4; i++) {
            int j = dd - i;
            if (j >= 1 && j <= 15) {
                float4 xs = (i == 0) ? xs0 : (i == 1) ? xs1 : (i == 2) ? xs2 : xs3;
                float p = xs.x*xd.x + xs.y*xd.y + xs.z*xd.z + xs.w*xd.w;
                p += __shfl_xor_sync(0xffffffffu, p, 16);
                p += __shfl_xor_sync(0xffffffffu, p, 8);
                if (lane < 8)
                    sp8[((rbase + i) * 15 + (j - 1)) * 8 + lane] = p;
            }
        }
    }
    __syncthreads();

    // Phase B1: log-kernel only: skk = -0.5*sqrt(d2)  (no exp!)
    for (int i = t; i < TR * 15; i += 256) {
        int rl = i / 15;
        float4 a  = *(const float4*)(sp8 + i * 8);
        float4 b4 = *(const float4*)(sp8 + i * 8 + 4);
        float dot = ((a.x + a.y) + (a.z + a.w)) + ((b4.x + b4.y) + (b4.z + b4.w));
        int jm1 = i - rl * 15;
        float d2 = fmaxf(snx[rl] + snx[rl + jm1 + 1] - 2.0f * dot, 0.0f);
        skk[i] = -0.5f * sqrtf(d2);
    }
    __syncthreads();

    // B2 scratch aliases the dead sp8 buffer
    float* satt = sp8;          // [512]
    float* se   = sp8 + 512;    // [512]
    float* sl   = sp8 + 1024;   // [512]

    // Phase B2a: att for all 512 (r,j) pairs
    #pragma unroll
    for (int rep = 0; rep < 2; rep++) {
        int i = t + rep * 256;
        int rl = i >> 4, j = i & 15;
        int r = r0 + rl;
        bool valid = (r + j) < NN;
        satt[i] = valid ? (sdsrc[rl] + sddst[rl + j]) : -1e9f;
    }
    __syncthreads();

    // Phase B2b: per-r max of att
    if (t < TR) {
        float m = satt[t * 16];
        #pragma unroll
        for (int j = 1; j < NFS; j++) m = fmaxf(m, satt[t * 16 + j]);
        sm[t] = m;
    }
    __syncthreads();

    // Phase B2c: softmax exps + log-scores, spread over all threads
    #pragma unroll
    for (int rep = 0; rep < 2; rep++) {
        int i = t + rep * 256;
        int rl = i >> 4, j = i & 15;
        float z = (satt[i] - sm[rl]) * invtau;
        se[i] = expf(z);
        sl[i] = (j == 0 ? 0.0f : skk[rl * 15 + (j - 1)]) + z;
    }
    __syncthreads();

    // Phase B2d: per-r sum + log-space max/argmax; 1 exp per r
    if (t < TR) {
        int r = r0 + t;
        if (r < NRES) {
            float ssum = 0.0f;
            #pragma unroll
            for (int j = 0; j < NFS; j++) ssum += se[t * 16 + j];
            float wl = sl[t * 16];
            float best = -3e38f;
            int bj = 1;
            #pragma unroll
            for (int j = 1; j < NFS; j++) {
                float lj = sl[t * 16 + j];
                wl = fmaxf(wl, lj);
                if (lj > best) { best = lj; bj = j; }
            }
            g_wv[b * NRES + r] = (expf(wl) / ssum) * g_sr[b * NN + r];
            sjmp[t] = bj;
        }
    }
    __syncthreads();

    // Tail: per-position within-segment exit + visited mask
    if (t < TR) {
        int r = r0 + t;
        if (r < NRES) {
            int e = r0 + TR; if (e > NRES) e = NRES;
            unsigned m = 0u;
            int p = r;
            while (p < e) { m |= 1u << (p - r0); p += sjmp[p - r0]; }
            g_exit[b * NN + r]  = p;
            g_maskf[b * NN + r] = m;
        }
    }
}

// -------- Kernel 4: staged chain + parallel compaction + pipelined gather ----
__global__ void k_chain(const float* __restrict__ x, float* __restrict__ out) {
    __shared__ float swv[NRES];
    __shared__ int   sord[NRES];
    __shared__ int   sexit[NRES];
    __shared__ int   sentry[16];
    __shared__ unsigned smask[16];
    __shared__ int   scnt[17];
    __shared__ int   sidx[NRES + 64];
    __shared__ float swt2[NRES + 64];
    __shared__ __align__(16) float part[16][NC];
    int b = blockIdx.x, t = threadIdx.x, w = t >> 5, lane = t & 31;  // 512 thr

    if (t < NRES) {
        swv[t]   = g_wv[b * NRES + t];
        sord[t]  = g_order[b * NN + t];
        sexit[t] = g_exit[b * NN + t];
    }
    if (t < 16) sentry[t] = -1;
    __syncthreads();

    // segment-to-segment hop: <=16 dependent LDS
    if (t == 0) {
        int p = 0;
        while (p < NRES) { sentry[p >> 5] = p; p = sexit[p]; }
    }
    __syncthreads();

    // entry masks straight from L2 (16 parallel LDG)
    if (t < 16) {
        int e = sentry[t];
        unsigned m = (e >= 0) ? g_maskf[b * NN + e] : 0u;
        smask[t] = m;
        scnt[t]  = __popc(m);
    }
    __syncthreads();
    if (t == 0) {
        int a = 0;
        #pragma unroll
        for (int i = 0; i < 16; i++) { int c = scnt[i]; scnt[i] = a; a += c; }
        scnt[16] = a;
    }
    __syncthreads();

    // fully parallel compaction from staged SMEM arrays
    if (t < NRES) {
        unsigned m = smask[t >> 5];
        if ((m >> (t & 31)) & 1u) {
            int slot = scnt[t >> 5] + __popc(m & ((1u << (t & 31)) - 1u));
            sidx[slot] = sord[t];
            swt2[slot] = swv[t];
        }
    }
    if (t >= 64 && t < 128) {   // zero-pad tail for over-read
        int n0 = scnt[16], k = t - 64;
        sidx[n0 + k] = 0;
        swt2[n0 + k] = 0.0f;
    }
    __syncthreads();

    // pipelined gather: each warp takes chunks of 4 independent rows
    int n = scnt[16];
    const float* xb = x + (size_t)b * NN * NC;
    float ax = 0.f, ay = 0.f, az = 0.f, a4 = 0.f;
    for (int base = w * 4; base < n; base += 64) {
        float u0 = swt2[base + 0], u1 = swt2[base + 1];
        float u2 = swt2[base + 2], u3 = swt2[base + 3];
        float4 v0 = *(const float4*)(xb + (size_t)sidx[base + 0] * NC + lane * 4);
        float4 v1 = *(const float4*)(xb + (size_t)sidx[base + 1] * NC + lane * 4);
        float4 v2 = *(const float4*)(xb + (size_t)sidx[base + 2] * NC + lane * 4);
        float4 v3 = *(const float4*)(xb + (size_t)sidx[base + 3] * NC + lane * 4);
        ax += u0*v0.x + u1*v1.x + u2*v2.x + u3*v3.x;
        ay += u0*v0.y + u1*v1.y + u2*v2.y + u3*v3.y;
        az += u0*v0.z + u1*v1.z + u2*v2.z + u3*v3.z;
        a4 += u0*v0.w + u1*v1.w + u2*v2.w + u3*v3.w;
    }
    part[w][lane * 4 + 0] = ax;
    part[w][lane * 4 + 1] = ay;
    part[w][lane * 4 + 2] = az;
    part[w][lane * 4 + 3] = a4;
    __syncthreads();

    if (t < NC) {
        float s = 0.0f;
        #pragma unroll
        for (int w2 = 0; w2 < 16; w2++) s += part[w2][t];
        out[b * NC + t] = s;
    }
}

extern "C" void kernel_launch(void* const* d_in, const int* in_sizes, int n_in,
                              void* d_out, int out_size) {
    const float* x   = (const float*)d_in[0];
    // d_in[1] = edge_index (unused by the reference forward pass)
    const float* sw  = (const float*)d_in[2];
    const float* ap  = (const float*)d_in[3];
    const int*   ep  = (const int*)d_in[4];
    float* out = (float*)d_out;

    k_scores<<<NBN / 8, 256>>>(x, sw, ap);
    k_sort<<<NB, NN>>>();
    dim3 gw((NRES + TR - 1) / TR, NB);
    k_windows<<<gw, 256>>>(x, ep);
    k_chain<<<NB, 512>>>(x, out);
}